// round 3
// baseline (speedup 1.0000x reference)
#include <cuda_runtime.h>
#include <math.h>

#define BB 64
#define MM 2048
#define CC 64
#define HH 128
#define NNZE 32768
#define H3 384

// -------- scratch (static device arrays; no runtime malloc) --------
__device__ int   g_rowcnt[BB*MM];
__device__ int   g_rowoff[BB*MM];
__device__ int   g_cluscnt[BB*CC];
__device__ int   g_clusoff[BB*CC];
__device__ int   g_rowperm[BB*MM];
__device__ int2  g_csr[BB*NNZE];
__device__ float g_xdec[BB*CC*H3];
__device__ float g_Q[BB*CC*HH];
__device__ float g_K[BB*CC*HH];
__device__ float g_V[BB*CC*HH];

// ============ K1: fused per-graph histogram + scan + scatter ============
__global__ void __launch_bounds__(1024) k_prep(const int* __restrict__ rows,
                                               const int* __restrict__ cols,
                                               const float* __restrict__ vals,
                                               const int* __restrict__ idx) {
    __shared__ int hist[MM];
    __shared__ int cur[MM];
    __shared__ int ss[1024];
    __shared__ int chist[CC];
    __shared__ int ccur[CC];
    int g = blockIdx.x, tid = threadIdx.x;
    hist[tid] = 0; hist[tid + 1024] = 0;
    if (tid < CC) chist[tid] = 0;
    __syncthreads();

    const int* r  = rows + g * NNZE;
    const int* ix = idx  + g * MM;
    for (int i = tid; i < NNZE; i += 1024) atomicAdd(&hist[r[i]], 1);
    int i0 = ix[tid], i1 = ix[tid + 1024];
    atomicAdd(&chist[i0], 1);
    atomicAdd(&chist[i1], 1);
    __syncthreads();

    int a = hist[2*tid], b = hist[2*tid + 1];
    int t = a + b;
    ss[tid] = t;
    __syncthreads();
    for (int off = 1; off < 1024; off <<= 1) {
        int v = (tid >= off) ? ss[tid - off] : 0;
        __syncthreads();
        ss[tid] += v;
        __syncthreads();
    }
    int excl = ss[tid] - t;
    int base = g * MM;
    g_rowoff[base + 2*tid]     = excl;      g_rowcnt[base + 2*tid]     = a;
    g_rowoff[base + 2*tid + 1] = excl + a;  g_rowcnt[base + 2*tid + 1] = b;
    cur[2*tid] = excl;  cur[2*tid + 1] = excl + a;
    if (tid == 0) {
        int acc = 0;
        for (int c = 0; c < CC; c++) {
            int cc = chist[c];
            g_clusoff[g*CC + c] = acc;
            g_cluscnt[g*CC + c] = cc;
            ccur[c] = acc;
            acc += cc;
        }
    }
    __syncthreads();

    const int*   c = cols + g * NNZE;
    const float* v = vals + g * NNZE;
    for (int i = tid; i < NNZE; i += 1024) {
        int rr = r[i];
        int p = atomicAdd(&cur[rr], 1);
        g_csr[g*NNZE + p] = make_int2(c[i], __float_as_int(v[i]));
    }
    {
        int p0 = atomicAdd(&ccur[i0], 1);
        g_rowperm[base + p0] = tid;
        int p1 = atomicAdd(&ccur[i1], 1);
        g_rowperm[base + p1] = tid + 1024;
    }
}

// ============ K2: SpMM + pooling, x slice staged in SMEM ============
// CTA = (graph, h-eighth). x slice [2048 rows x 16 floats] = 128KB in smem:
// every edge gather is an LDS, never a cache gamble. Warp owns 2 clusters;
// lane = (edge-subindex h in 0..3, float2-index fl in 0..7) -> 4 edges/iter.
// Row value rebuilt via 2 shfl_xor levels; pooling in registers; epilogue
// writes [mean|max|sum] straight into g_xdec.
__global__ void __launch_bounds__(1024) k_spmm(const float* __restrict__ x) {
    extern __shared__ float2 xs[];          // 2048 * 8 float2 = 128KB
    int g = blockIdx.x >> 3, s = blockIdx.x & 7;
    int tid = threadIdx.x;

    // stage x[g][:, s*16 .. s*16+16) -> smem
    const float4* xg4 = (const float4*)x + (size_t)g * MM * 32;
    float4* xs4 = (float4*)xs;
    #pragma unroll
    for (int i = tid; i < MM * 4; i += 1024) {
        int row = i >> 2, part = i & 3;
        xs4[row * 4 + part] = __ldg(&xg4[row * 32 + s * 4 + part]);
    }
    __syncthreads();

    int wid = tid >> 5, lane = tid & 31;
    int h  = lane >> 3;      // edge sub-index 0..3
    int fl = lane & 7;       // float2 index 0..7
    const int2* csr  = g_csr     + (size_t)g * NNZE;
    const int*  perm = g_rowperm + g * MM;
    const int*  roff = g_rowoff  + g * MM;
    const int*  rcnt = g_rowcnt  + g * MM;

    #pragma unroll
    for (int half = 0; half < 2; half++) {
        int c = wid + half * 32;
        int coff = g_clusoff[g*CC + c];
        int cn   = g_cluscnt[g*CC + c];
        float2 sm2 = make_float2(0.f, 0.f);
        float2 mx2 = make_float2(-INFINITY, -INFINITY);
        for (int i = 0; i < cn; i++) {
            int row = perm[coff + i];
            int eo = roff[row], el = rcnt[row];
            float2 acc = make_float2(0.f, 0.f);
            int nmain = el >> 2;
            const int2* ep = csr + eo + h;
            for (int it = 0; it < nmain; it++) {
                int2 p = __ldg(ep + it * 4);          // 4 distinct 8B broadcasts
                float v = __int_as_float(p.y);
                float2 xv = xs[p.x * 8 + fl];
                acc.x += v * xv.x; acc.y += v * xv.y;
            }
            int rem = el & 3;
            if (rem) {
                float v = 0.f; int cc2 = 0;
                if (h < rem) {
                    int2 p = __ldg(&csr[eo + (el & ~3) + h]);
                    v = __int_as_float(p.y); cc2 = p.x;
                }
                float2 xv = xs[cc2 * 8 + fl];
                acc.x += v * xv.x; acc.y += v * xv.y;
            }
            // combine the 4 edge sub-accumulators (lanes differ in bits 3,4)
            acc.x += __shfl_xor_sync(0xFFFFFFFFu, acc.x, 8);
            acc.y += __shfl_xor_sync(0xFFFFFFFFu, acc.y, 8);
            acc.x += __shfl_xor_sync(0xFFFFFFFFu, acc.x, 16);
            acc.y += __shfl_xor_sync(0xFFFFFFFFu, acc.y, 16);
            sm2.x += acc.x; sm2.y += acc.y;
            mx2.x = fmaxf(mx2.x, acc.x); mx2.y = fmaxf(mx2.y, acc.y);
        }
        if (h == 0) {     // lanes 0..7 hold the full result
            float cf = fmaxf((float)cn, 1.f);
            float* xd = g_xdec + (g*CC + c) * H3 + s * 16 + fl * 2;
            xd[0]        = sm2.x / cf;  xd[1]        = sm2.y / cf;
            xd[HH]       = mx2.x;       xd[HH + 1]   = mx2.y;
            xd[2*HH]     = sm2.x;       xd[2*HH + 1] = sm2.y;
        }
    }
}

// ============ K3: Q/K/V = x_dec @ W with packed f32x2 FMA ============
__device__ __forceinline__ void ffma2(unsigned long long& d,
                                      unsigned long long a,
                                      unsigned long long b) {
    asm("fma.rn.f32x2 %0, %1, %2, %0;" : "+l"(d) : "l"(a), "l"(b));
}
__device__ __forceinline__ unsigned long long pack2(float v) {
    unsigned long long r;
    asm("mov.b64 %0, {%1, %1};" : "=l"(r) : "f"(v));
    return r;
}

#define XS_LD 68
__global__ void __launch_bounds__(256) k_gemm(const float* __restrict__ Wq,
                                              const float* __restrict__ Wk,
                                              const float* __restrict__ Wv) {
    extern __shared__ float sm[];
    float* xsA = sm;                // [64 k][68 pad] transposed A tile
    float* ws  = sm + 64 * XS_LD;   // [64 k][128 h] W tile
    int g = blockIdx.x, which = blockIdx.y;
    const float* W = (which == 0) ? Wq : (which == 1) ? Wk : Wv;
    float* out = ((which == 0) ? g_Q : (which == 1) ? g_K : g_V) + g * CC * HH;
    const float* xd = g_xdec + g * CC * H3;
    int tid = threadIdx.x;
    int ty = tid >> 4, tx = tid & 15;

    unsigned long long acc[4][4];
    #pragma unroll
    for (int i = 0; i < 4; i++)
        #pragma unroll
        for (int j = 0; j < 4; j++) acc[i][j] = 0ull;

    for (int kt = 0; kt < H3; kt += 64) {
        __syncthreads();
        for (int i = tid; i < 64 * 64; i += 256) {
            int rr = i >> 6, kk = i & 63;
            xsA[kk * XS_LD + rr] = xd[rr * H3 + kt + kk];
        }
        const float4* wsrc = (const float4*)(W + kt * HH);
        for (int i = tid; i < 64 * HH / 4; i += 256) ((float4*)ws)[i] = wsrc[i];
        __syncthreads();
        #pragma unroll 4
        for (int kk = 0; kk < 64; kk++) {
            float4 av = *(const float4*)&xsA[kk * XS_LD + ty * 4];
            const unsigned long long* bp =
                (const unsigned long long*)&ws[kk * HH + tx * 8];
            unsigned long long pa0 = pack2(av.x), pa1 = pack2(av.y);
            unsigned long long pa2 = pack2(av.z), pa3 = pack2(av.w);
            #pragma unroll
            for (int j = 0; j < 4; j++) {
                unsigned long long b = bp[j];
                ffma2(acc[0][j], pa0, b);
                ffma2(acc[1][j], pa1, b);
                ffma2(acc[2][j], pa2, b);
                ffma2(acc[3][j], pa3, b);
            }
        }
    }
    #pragma unroll
    for (int i = 0; i < 4; i++) {
        unsigned long long* o =
            (unsigned long long*)&out[(ty*4 + i) * HH + tx * 8];
        #pragma unroll
        for (int j = 0; j < 4; j++) o[j] = acc[i][j];
    }
}

// ============ K4: attention, row-split grid (64 graphs x 2 halves) ======
__global__ void __launch_bounds__(256) k_attn(float* __restrict__ out) {
    extern __shared__ float sm[];
    float* Qs = sm;                   // 32 * 132
    float* Ks = Qs + 32 * 132;        // 64 * 132
    float* Vs = Ks + 64 * 132;        // 64 * 132
    float* Ss = Vs + 64 * 132;        // 32 * 68
    int g = blockIdx.x, rh = blockIdx.y * 32, tid = threadIdx.x;
    const float* Qg = g_Q + g * CC * HH + rh * HH;
    const float* Kg = g_K + g * CC * HH;
    const float* Vg = g_V + g * CC * HH;

    for (int i = tid; i < 32 * HH; i += 256) {
        int r = i >> 7, hh = i & 127;
        Qs[r*132 + hh] = Qg[i];
    }
    for (int i = tid; i < CC * HH; i += 256) {
        int r = i >> 7, hh = i & 127;
        Ks[r*132 + hh] = Kg[i];
        Vs[r*132 + hh] = Vg[i];
    }
    __syncthreads();

    int r = tid & 31, grp = tid >> 5;      // 32 rows x 8 col-groups
    {
        float sacc[8];
        #pragma unroll
        for (int cc = 0; cc < 8; cc++) sacc[cc] = 0.f;
        const float4* q4 = (const float4*)Qs + r * 33;
        const float4* k4 = (const float4*)Ks;
        #pragma unroll 2
        for (int h4 = 0; h4 < 32; h4++) {
            float4 q = q4[h4];
            #pragma unroll
            for (int cc = 0; cc < 8; cc++) {
                float4 k = k4[(grp*8 + cc) * 33 + h4];
                sacc[cc] += q.x*k.x + q.y*k.y + q.z*k.z + q.w*k.w;
            }
        }
        const float scale = 0.08838834764831845f;   // 1/sqrt(128)
        #pragma unroll
        for (int cc = 0; cc < 8; cc++) Ss[r*68 + grp*8 + cc] = sacc[cc] * scale;
    }
    __syncthreads();
    if (tid < 32) {
        float m = -INFINITY;
        for (int c = 0; c < CC; c++) m = fmaxf(m, Ss[tid*68 + c]);
        float sum = 0.f;
        for (int c = 0; c < CC; c++) {
            float e = __expf(Ss[tid*68 + c] - m);
            Ss[tid*68 + c] = e;
            sum += e;
        }
        float inv = 1.f / sum;
        for (int c = 0; c < CC; c++) Ss[tid*68 + c] *= inv;
    }
    __syncthreads();
    {
        float4 acc[4];
        #pragma unroll
        for (int j = 0; j < 4; j++) acc[j] = make_float4(0.f, 0.f, 0.f, 0.f);
        const float4* v4 = (const float4*)Vs;
        for (int c = 0; c < CC; c++) {
            float p = Ss[r*68 + c];
            const float4* vrow = v4 + c * 33 + grp * 4;
            #pragma unroll
            for (int j = 0; j < 4; j++) {
                float4 v = vrow[j];
                acc[j].x += p * v.x; acc[j].y += p * v.y;
                acc[j].z += p * v.z; acc[j].w += p * v.w;
            }
        }
        float4* o4 = (float4*)out + g * 2048 + (rh + r) * 32 + grp * 4;
        #pragma unroll
        for (int j = 0; j < 4; j++) o4[j] = acc[j];
    }
}

extern "C" void kernel_launch(void* const* d_in, const int* in_sizes, int n_in,
                              void* d_out, int out_size) {
    const float* x    = (const float*)d_in[0];
    const int*   rows = (const int*)d_in[3];
    const int*   cols = (const int*)d_in[4];
    const float* vals = (const float*)d_in[5];
    const int*   idx  = (const int*)d_in[6];
    const float* Wq   = (const float*)d_in[7];
    const float* Wk   = (const float*)d_in[8];
    const float* Wv   = (const float*)d_in[9];
    float* out = (float*)d_out;

    static const int SPMM_SMEM = MM * 16 * 4;                       // 131072 B
    static const int GEMM_SMEM = (64*XS_LD + 64*HH) * 4;            // 50176 B
    static const int ATTN_SMEM = ((32 + 2*64) * 132 + 32*68) * 4;   // 93184 B
    cudaFuncSetAttribute(k_spmm, cudaFuncAttributeMaxDynamicSharedMemorySize, SPMM_SMEM);
    cudaFuncSetAttribute(k_gemm, cudaFuncAttributeMaxDynamicSharedMemorySize, GEMM_SMEM);
    cudaFuncSetAttribute(k_attn, cudaFuncAttributeMaxDynamicSharedMemorySize, ATTN_SMEM);

    k_prep<<<BB, 1024>>>(rows, cols, vals, idx);
    k_spmm<<<BB * 8, 1024, SPMM_SMEM>>>(x);
    k_gemm<<<dim3(BB, 3), 256, GEMM_SMEM>>>(Wq, Wk, Wv);
    k_attn<<<dim3(BB, 2), 256, ATTN_SMEM>>>(out);
}